// round 15
// baseline (speedup 1.0000x reference)
#include <cuda_runtime.h>
#include <cstdint>
#include <math.h>

#define N_B 64
#define T_T 512
#define D_D 512
#define H_H 512

// Scratch (device globals: allocation-free per harness rules)
__device__ float g_hbuf[2 * 8 * 8 * 512];   // double-buffered compact h exchange
__device__ unsigned int g_sync[8];          // per-group step counters

__global__ void init_sync_kernel() {
    if (threadIdx.x < 8) g_sync[threadIdx.x] = 0u;
}

// ---- packed fp32x2 helpers (Blackwell FFMA2 path) ----
__device__ __forceinline__ unsigned long long ffma2(
    unsigned long long a, unsigned long long b, unsigned long long c) {
    unsigned long long d;
    asm("fma.rn.f32x2 %0, %1, %2, %3;" : "=l"(d) : "l"(a), "l"(b), "l"(c));
    return d;
}
__device__ __forceinline__ unsigned long long pack2(float lo, float hi) {
    unsigned long long r;
    asm("mov.b64 %0, {%1, %2};" : "=l"(r) : "f"(lo), "f"(hi));
    return r;
}

// ---------------------------------------------------------------------------
// Fused RNN, register-direct activations.
// 128 CTAs = 8 groups (8 batch rows) x 16 column slices (32 cols).
// Wh and Wx slices SMEM-resident (bank-staggered). h and x are loaded
// DIRECTLY into registers (each thread needs only its own (row, 32-k) chunk),
// eliminating all activation SMEM staging and its barriers. The x-slab for
// t+1 (independent of h_t) runs between the h LDG issue and the h-slab,
// covering the h load latency. 2 syncthreads/step (k-split reduction only).
// ---------------------------------------------------------------------------
#define KPSTRIDE 1032            // 32k*32cols + 8 stagger floats per kp chunk
#define SW_F     (16 * KPSTRIDE) // 16512 floats per weight slice
#define RPAD     288             // 8*36 reduction row per kp
#define SMEM_BYTES ((2 * SW_F + 16 * RPAD) * 4)   // 150528 B

// 16-col x 32-k packed-FMA slab reading activations from 8 float4 registers
__device__ __forceinline__ void slab_reg(
    const float4* __restrict__ v8,        // 32 activation values (registers)
    const float* __restrict__ wb,         // &sW[kp*KPSTRIDE + cg*16]
    unsigned long long* __restrict__ acc)
{
#pragma unroll
    for (int q8 = 0; q8 < 8; q8++) {
        float4 h4 = v8[q8];
#pragma unroll
        for (int q = 0; q < 4; q++) {
            float hv = (q == 0) ? h4.x : (q == 1) ? h4.y : (q == 2) ? h4.z : h4.w;
            unsigned long long h2 = pack2(hv, hv);
            const float* wp = wb + (((q8 << 2) + q) << 5);
            ulonglong2 wA = *(const ulonglong2*)(wp + 0);
            ulonglong2 wB = *(const ulonglong2*)(wp + 4);
            ulonglong2 wC = *(const ulonglong2*)(wp + 8);
            ulonglong2 wD = *(const ulonglong2*)(wp + 12);
            acc[0] = ffma2(h2, wA.x, acc[0]);
            acc[1] = ffma2(h2, wA.y, acc[1]);
            acc[2] = ffma2(h2, wB.x, acc[2]);
            acc[3] = ffma2(h2, wB.y, acc[3]);
            acc[4] = ffma2(h2, wC.x, acc[4]);
            acc[5] = ffma2(h2, wC.y, acc[5]);
            acc[6] = ffma2(h2, wD.x, acc[6]);
            acc[7] = ffma2(h2, wD.y, acc[7]);
        }
    }
}

__global__ __launch_bounds__(256, 1) void rnn_fused_kernel(
    const float* __restrict__ x,    // (64, 512, 512)
    const float* __restrict__ h0,   // (64, 512)
    const float* __restrict__ Wh,   // (512, 512)
    const float* __restrict__ Wx,   // (512, 512)
    const float* __restrict__ bias, // (512,)
    float* __restrict__ out)        // (64, 512, 512)
{
    extern __shared__ float smem[];
    float* sWh  = smem;                     // [16 kp][32 k][32 cols] stride 1032
    float* sWx  = sWh + SW_F;
    float* sRed = sWx + SW_F;               // [16][8][36]

    const int tid = threadIdx.x;
    const int g   = blockIdx.x >> 4;        // batch group 0..7
    const int c   = blockIdx.x & 15;        // column slice 0..15
    const int c0  = c << 5;
    const int n0  = g << 3;

    // Load both weight slices into bank-staggered layout
    for (int i = tid; i < 4096; i += 256) {
        int k = i >> 3, j4 = (i & 7) << 2;
        int d = (k >> 5) * KPSTRIDE + (k & 31) * 32 + j4;
        *(float4*)&sWh[d] = *(const float4*)&Wh[(size_t)k * H_H + c0 + j4];
        *(float4*)&sWx[d] = *(const float4*)&Wx[(size_t)k * H_H + c0 + j4];
    }

    const int r   = tid & 7;                // batch row for slab
    const int cg  = (tid >> 3) & 1;         // column half (16 cols)
    const int kp  = tid >> 4;               // k-split 0..15
    const int k0  = kp << 5;
    const int or_ = tid >> 5;               // owned output row
    const int oc_ = tid & 31;               // owned output col

    const float bcol = bias[c0 + oc_];
    size_t oidx = ((size_t)(n0 + or_) * T_T) * H_H + c0 + oc_;

    const float* whb = &sWh[kp * KPSTRIDE + (cg << 4)];
    const float* wxb = &sWx[kp * KPSTRIDE + (cg << 4)];
    unsigned int* syncp = &g_sync[g];

    // this thread's x chunk base: x[n0+r][t][k0..k0+31]
    const float* xbase = x + (size_t)(n0 + r) * T_T * D_D + k0;
    // this thread's h chunk base in the exchange buffer
    const int hoff = (r << 9) + k0;

    // prologue: load x tile 0 chunk, compute xacc(t=0)
    float4 xreg[8];
#pragma unroll
    for (int q = 0; q < 8; q++)
        xreg[q] = __ldcg((const float4*)xbase + q);

    __syncthreads();    // weights ready

    unsigned long long xacc[8];
#pragma unroll
    for (int j = 0; j < 8; j++) xacc[j] = 0ull;
    slab_reg(xreg, wxb, xacc);

    // load x tile 1 chunk (consumed in iter 0's x-slab)
#pragma unroll
    for (int q = 0; q < 8; q++)
        xreg[q] = __ldcg((const float4*)(xbase + D_D) + q);

    for (int t = 0; t < T_T; t++) {
        // ---- wait for peers' h_{t-1} (all threads poll; usually ready) ----
        if (t > 0) {
            const unsigned int target = (unsigned int)t << 4;
            unsigned int fv;
            do {
                asm volatile("ld.acquire.gpu.global.u32 %0, [%1];"
                             : "=r"(fv) : "l"(syncp) : "memory");
            } while (fv < target);
        }

        // ---- issue h LDGs (latency covered by the x-slab below) ----
        float4 hreg[8];
        {
            const float* hp = (t == 0)
                ? (h0 + (size_t)(n0 + r) * H_H + k0)
                : (g_hbuf + (size_t)((((t - 1) & 1) << 3) + g) * 4096 + hoff);
#pragma unroll
            for (int q = 0; q < 8; q++)
                hreg[q] = __ldcg((const float4*)hp + q);
        }

        unsigned long long acc[8];
#pragma unroll
        for (int j = 0; j < 8; j++) acc[j] = xacc[j];

        // ---- x-slab for t+1 (independent; fills h-load latency) ----
        if (t + 1 < T_T) {
#pragma unroll
            for (int j = 0; j < 8; j++) xacc[j] = 0ull;
            slab_reg(xreg, wxb, xacc);
            // reload xreg with tile t+2 (arrives by next iteration)
            if (t + 2 < T_T) {
                const float* xp = xbase + (size_t)(t + 2) * D_D;
#pragma unroll
                for (int q = 0; q < 8; q++)
                    xreg[q] = __ldcg((const float4*)xp + q);
            }
        }

        // ---- h-slab (hreg has arrived) ----
        slab_reg(hreg, whb, acc);

        // ---- k-split partials ----
        {
            float* dst = &sRed[kp * RPAD + r * 36 + (cg << 4)];
            *(ulonglong2*)(dst + 0)  = make_ulonglong2(acc[0], acc[1]);
            *(ulonglong2*)(dst + 4)  = make_ulonglong2(acc[2], acc[3]);
            *(ulonglong2*)(dst + 8)  = make_ulonglong2(acc[4], acc[5]);
            *(ulonglong2*)(dst + 12) = make_ulonglong2(acc[6], acc[7]);
        }
        __syncthreads();

        // ---- reduce 16 partials (fixed order), bias, tanh, store ----
        float v = bcol;
#pragma unroll
        for (int p = 0; p < 16; p++)
            v += sRed[p * RPAD + or_ * 36 + oc_];
        v = tanhf(v);
        out[oidx] = v;
        oidx += H_H;

        if (t < T_T - 1) {
            // publish h_t (parity t&1)
            g_hbuf[(size_t)(((t & 1) << 3) + g) * 4096 + (or_ << 9) + c0 + oc_] = v;
            __syncthreads();    // all publishes issued + sRed reads done
            if (tid == 0) {
                asm volatile("red.release.gpu.global.add.u32 [%0], %1;"
                             :: "l"(syncp), "r"(1u) : "memory");
            }
        }
    }
}

// ---------------------------------------------------------------------------
extern "C" void kernel_launch(void* const* d_in, const int* in_sizes, int n_in,
                              void* d_out, int out_size) {
    (void)in_sizes; (void)n_in; (void)out_size;
    const float* x  = (const float*)d_in[0];
    const float* h0 = (const float*)d_in[1];
    const float* Wx = (const float*)d_in[2];
    const float* Wh = (const float*)d_in[3];
    const float* b  = (const float*)d_in[4];
    float* out = (float*)d_out;

    init_sync_kernel<<<1, 32>>>();

    cudaFuncSetAttribute((const void*)rnn_fused_kernel,
                         cudaFuncAttributeMaxDynamicSharedMemorySize,
                         SMEM_BYTES);
    rnn_fused_kernel<<<128, 256, SMEM_BYTES>>>(x, h0, Wh, Wx, b, out);
}

// round 16
// speedup vs baseline: 1.1205x; 1.1205x over previous
#include <cuda_runtime.h>
#include <cstdint>
#include <math.h>

#define N_B 64
#define T_T 512
#define D_D 512
#define H_H 512

// 67 MB scratch for xWx (device global: allocation-free per harness rules)
__device__ float g_xwx[(size_t)N_B * T_T * H_H];

// ---- packed fp32x2 helpers (Blackwell FFMA2 path) ----
__device__ __forceinline__ unsigned long long ffma2(
    unsigned long long a, unsigned long long b, unsigned long long c) {
    unsigned long long d;
    asm("fma.rn.f32x2 %0, %1, %2, %3;" : "=l"(d) : "l"(a), "l"(b), "l"(c));
    return d;
}
__device__ __forceinline__ unsigned long long fadd2(
    unsigned long long a, unsigned long long b) {
    unsigned long long d;
    asm("add.rn.f32x2 %0, %1, %2;" : "=l"(d) : "l"(a), "l"(b));
    return d;
}
__device__ __forceinline__ unsigned long long pack2(float lo, float hi) {
    unsigned long long r;
    asm("mov.b64 %0, {%1, %2};" : "=l"(r) : "f"(lo), "f"(hi));
    return r;
}

// ---------------------------------------------------------------------------
// Phase 1: g_xwx[m][h] = x[m][:] @ Wx[:][h] + b[h]  (32768 x 512 SGEMM)
// (unchanged from the 1811us best kernel)
// ---------------------------------------------------------------------------
#define BM 128
#define BN 128
#define BK 16

__global__ __launch_bounds__(256, 2) void xwx_gemm_kernel(
    const float* __restrict__ A,
    const float* __restrict__ B,
    const float* __restrict__ bias)
{
    __shared__ float As[BK][BM + 4];
    __shared__ float Bs[BK][BN + 4];

    const int tid = threadIdx.x;
    const int bm = blockIdx.y * BM;
    const int bn = blockIdx.x * BN;

    const int ty = tid >> 4;
    const int tx = tid & 15;

    const int aRow = tid >> 2;
    const int aCol = (tid & 3) << 2;
    const int bRow = tid >> 5;
    const int bCol = (tid & 31) << 2;

    unsigned long long acc2[8][4];
#pragma unroll
    for (int i = 0; i < 8; i++)
#pragma unroll
        for (int j = 0; j < 4; j++) acc2[i][j] = 0ull;

    for (int kt = 0; kt < D_D; kt += BK) {
#pragma unroll
        for (int rr = 0; rr < BM; rr += 64) {
            float4 a = *(const float4*)&A[(size_t)(bm + aRow + rr) * D_D + kt + aCol];
            As[aCol + 0][aRow + rr] = a.x;
            As[aCol + 1][aRow + rr] = a.y;
            As[aCol + 2][aRow + rr] = a.z;
            As[aCol + 3][aRow + rr] = a.w;
        }
#pragma unroll
        for (int rr = 0; rr < BK; rr += 8) {
            float4 b4 = *(const float4*)&B[(size_t)(kt + bRow + rr) * H_H + bn + bCol];
            *(float4*)&Bs[bRow + rr][bCol] = b4;
        }
        __syncthreads();

#pragma unroll
        for (int k = 0; k < BK; k++) {
            float4 a0 = *(const float4*)&As[k][ty * 4];
            float4 a1 = *(const float4*)&As[k][64 + ty * 4];
            ulonglong2 b01 = *(const ulonglong2*)&Bs[k][tx * 4];
            ulonglong2 b23 = *(const ulonglong2*)&Bs[k][64 + tx * 4];

            unsigned long long av[8];
            av[0] = pack2(a0.x, a0.x); av[1] = pack2(a0.y, a0.y);
            av[2] = pack2(a0.z, a0.z); av[3] = pack2(a0.w, a0.w);
            av[4] = pack2(a1.x, a1.x); av[5] = pack2(a1.y, a1.y);
            av[6] = pack2(a1.z, a1.z); av[7] = pack2(a1.w, a1.w);

#pragma unroll
            for (int i = 0; i < 8; i++) {
                acc2[i][0] = ffma2(av[i], b01.x, acc2[i][0]);
                acc2[i][1] = ffma2(av[i], b01.y, acc2[i][1]);
                acc2[i][2] = ffma2(av[i], b23.x, acc2[i][2]);
                acc2[i][3] = ffma2(av[i], b23.y, acc2[i][3]);
            }
        }
        __syncthreads();
    }

#pragma unroll
    for (int i = 0; i < 8; i++) {
        int row = bm + ((i < 4) ? (ty * 4 + i) : (64 + ty * 4 + (i - 4)));
#pragma unroll
        for (int jj = 0; jj < 2; jj++) {
            int col = bn + jj * 64 + tx * 4;
            ulonglong2 bb = *(const ulonglong2*)&bias[col];
            ulonglong2 v;
            v.x = fadd2(acc2[i][jj * 2 + 0], bb.x);
            v.y = fadd2(acc2[i][jj * 2 + 1], bb.y);
            *(ulonglong2*)&g_xwx[(size_t)row * H_H + col] = v;
        }
    }
}

// ---------------------------------------------------------------------------
// Phase 2: cluster-pull scan. 16 clusters x 8 CTAs; cluster = 4 batch rows,
// CTA = 64-col Wh slice (SMEM). Per step: slab from local sHa, k-split
// reduce, write own 4x64 slice LOCALLY, HW cluster barrier, then PULL the 7
// peer slices via ld.shared::cluster into sHa. No L2 in the h loop.
// ---------------------------------------------------------------------------
#define KPCH   2052              // 32k*64cols + 4 pad  (== 4 mod 32)
#define SW_F   (16 * KPCH)       // 32832 floats
#define HCS    36                // h chunk stride (32 data + 4 pad)
#define HROW   (16 * HCS + 8)    // 584 floats per h row
#define SH_F   (4 * HROW)        // 2336
#define RPW    68                // reduction row stride (64 + 4)
#define RCH    (4 * RPW)         // 272 floats per kp / per slice buffer
#define SRED_F (16 * RCH)        // 4352
#define SSL_F  (2 * RCH)         // 544 (double-buffered own slice)
#define SMEM_SCAN_BYTES ((SW_F + SH_F + SRED_F + SSL_F) * 4)   // 160256 B

__global__ __launch_bounds__(256, 1) __cluster_dims__(8, 1, 1)
void rnn_scan_kernel(const float* __restrict__ h0,
                     const float* __restrict__ Wh,
                     float* __restrict__ out)
{
    extern __shared__ float smem[];
    float* sWh  = smem;                 // [16 kp][32 k][64 cols] stride 2052
    float* sHa  = smem + SW_F;          // [4 rows][16 chunks][36]
    float* sRed = sHa + SH_F;           // [16 kp][4 rows][68]
    float* sSl  = sRed + SRED_F;        // [2 par][4 rows][68] own output slice

    const int tid = threadIdx.x;
    const int g   = blockIdx.x >> 3;    // cluster / batch group 0..15
    const int c   = blockIdx.x & 7;     // rank / column slice 0..7
    const int c0  = c << 6;
    const int n0  = g << 2;

    // Load Wh slice into chunked layout: sWh[(k>>5)*KPCH + (k&31)*64 + j]
    for (int i = tid; i < 8192; i += 256) {
        int k = i >> 4, j4 = (i & 15) << 2;
        *(float4*)&sWh[(k >> 5) * KPCH + (k & 31) * 64 + j4] =
            *(const float4*)&Wh[(size_t)k * H_H + c0 + j4];
    }
    // Load h0 rows n0..n0+3 into chunked sHa
    for (int i = tid; i < 512; i += 256) {
        int row = i >> 7, q4 = i & 127;
        *(float4*)&sHa[row * HROW + (q4 >> 3) * HCS + ((q4 & 7) << 2)] =
            *(const float4*)&h0[(size_t)(n0 + row) * H_H + (q4 << 2)];
    }

    // warp-level mapping: conflict-free weight LDS (kp varies in-warp)
    const int warp = tid >> 5, lane = tid & 31;
    const int cg  = warp & 3;            // 16-col group
    const int kp  = ((warp >> 2) << 3) + (lane >> 2);   // 0..15
    const int r   = lane & 3;            // batch row for slab
    const int or_ = tid >> 6;            // owned output row (0..3)
    const int oc_ = tid & 63;            // owned output col (0..63)

    unsigned int ssl_u32;
    asm("{ .reg .u64 t; cvta.to.shared.u64 t, %1; cvt.u32.u64 %0, t; }"
        : "=r"(ssl_u32) : "l"(sSl));

    size_t oidx = ((size_t)(n0 + or_) * T_T) * H_H + c0 + oc_;
    float xv = __ldcg(&g_xwx[oidx]);     // xwx for t=0 (bias folded in)

    const float* whb = &sWh[kp * KPCH + (cg << 4)];
    const float* hgb = &sHa[r * HROW + kp * HCS];

    __syncthreads();

    for (int t = 0; t < T_T; t++) {
        if (t > 0) {
            // ---- PULL peer slices (parity (t-1)&1) into chunked sHa ----
            const int par = (t - 1) & 1;
#pragma unroll
            for (int ii = 0; ii < 2; ii++) {
                int i  = tid + (ii << 8);
                int row = i >> 7, q4 = i & 127;
                int rk = q4 >> 4, j4 = (q4 & 15) << 2;
                unsigned int loc = ssl_u32 +
                    (unsigned int)((par * RCH + row * RPW + j4) << 2);
                unsigned int ra;
                asm("mapa.shared::cluster.u32 %0, %1, %2;"
                    : "=r"(ra) : "r"(loc), "r"(rk));
                float vx, vy, vz, vw;
                asm volatile("ld.shared::cluster.v4.f32 {%0,%1,%2,%3}, [%4];"
                             : "=f"(vx), "=f"(vy), "=f"(vz), "=f"(vw)
                             : "r"(ra));
                float* d = &sHa[row * HROW + (q4 >> 3) * HCS + ((q4 & 7) << 2)];
                d[0] = vx; d[1] = vy; d[2] = vz; d[3] = vw;
            }
            __syncthreads();
        }

        // ---- load this thread's 32 h values into registers (local LDS) ----
        float4 hreg[8];
#pragma unroll
        for (int u = 0; u < 8; u++)
            hreg[u] = *(const float4*)(hgb + (u << 2));

        // ---- packed FMA slab: 16 cols x 32 k ----
        unsigned long long acc[8];
#pragma unroll
        for (int j = 0; j < 8; j++) acc[j] = 0ull;
#pragma unroll
        for (int q8 = 0; q8 < 8; q8++) {
            float4 h4 = hreg[q8];
#pragma unroll
            for (int q = 0; q < 4; q++) {
                float hv = (q == 0) ? h4.x : (q == 1) ? h4.y : (q == 2) ? h4.z : h4.w;
                unsigned long long h2 = pack2(hv, hv);
                const float* wp = whb + (((q8 << 2) + q) << 6);
                ulonglong2 wA = *(const ulonglong2*)(wp + 0);
                ulonglong2 wB = *(const ulonglong2*)(wp + 4);
                ulonglong2 wC = *(const ulonglong2*)(wp + 8);
                ulonglong2 wD = *(const ulonglong2*)(wp + 12);
                acc[0] = ffma2(h2, wA.x, acc[0]);
                acc[1] = ffma2(h2, wA.y, acc[1]);
                acc[2] = ffma2(h2, wB.x, acc[2]);
                acc[3] = ffma2(h2, wB.y, acc[3]);
                acc[4] = ffma2(h2, wC.x, acc[4]);
                acc[5] = ffma2(h2, wC.y, acc[5]);
                acc[6] = ffma2(h2, wD.x, acc[6]);
                acc[7] = ffma2(h2, wD.y, acc[7]);
            }
        }

        // ---- k-split partials ----
        {
            float* dst = &sRed[kp * RCH + r * RPW + (cg << 4)];
            *(ulonglong2*)(dst + 0)  = make_ulonglong2(acc[0], acc[1]);
            *(ulonglong2*)(dst + 4)  = make_ulonglong2(acc[2], acc[3]);
            *(ulonglong2*)(dst + 8)  = make_ulonglong2(acc[4], acc[5]);
            *(ulonglong2*)(dst + 12) = make_ulonglong2(acc[6], acc[7]);
        }
        __syncthreads();

        // ---- reduce 16 partials (fixed order), add xwx, tanh, store ----
        float v = xv;
#pragma unroll
        for (int p = 0; p < 16; p++)
            v += sRed[p * RCH + or_ * RPW + oc_];
        v = tanhf(v);
        out[oidx] = v;
        oidx += H_H;

        if (t < T_T - 1) {
            // write own slice LOCALLY (no remote stores to drain)
            sSl[(t & 1) * RCH + or_ * RPW + oc_] = v;
            asm volatile("barrier.cluster.arrive.release.aligned;" ::: "memory");
            // prefetch next xwx between arrive and wait
            xv = __ldcg(&g_xwx[oidx]);
            asm volatile("barrier.cluster.wait.acquire.aligned;" ::: "memory");
        }
    }
}

// ---------------------------------------------------------------------------
extern "C" void kernel_launch(void* const* d_in, const int* in_sizes, int n_in,
                              void* d_out, int out_size) {
    (void)in_sizes; (void)n_in; (void)out_size;
    const float* x  = (const float*)d_in[0];
    const float* h0 = (const float*)d_in[1];
    const float* Wx = (const float*)d_in[2];
    const float* Wh = (const float*)d_in[3];
    const float* b  = (const float*)d_in[4];
    float* out = (float*)d_out;

    dim3 g1(H_H / BN, (N_B * T_T) / BM);   // (4, 256)
    xwx_gemm_kernel<<<g1, 256>>>(x, Wx, b);

    cudaFuncSetAttribute((const void*)rnn_scan_kernel,
                         cudaFuncAttributeMaxDynamicSharedMemorySize,
                         SMEM_SCAN_BYTES);
    rnn_scan_kernel<<<128, 256, SMEM_SCAN_BYTES>>>(h0, Wh, out);
}